// round 2
// baseline (speedup 1.0000x reference)
#include <cuda_runtime.h>
#include <cstdint>

#define N_NODES 50000
#define N_EDGES 600000
#define DIM 128

// Scratch: per-node attention denominator (sum of exp weights)
__device__ float g_denom[N_NODES];

// ---------------------------------------------------------------------------
// K0: zero the aggregation buffer (d_out doubles as agg scratch) and g_denom
// ---------------------------------------------------------------------------
__global__ void zero_kernel(float4* __restrict__ out4) {
    int idx = blockIdx.x * blockDim.x + threadIdx.x;
    int stride = gridDim.x * blockDim.x;
    const int n4 = N_NODES * DIM / 4;
    float4 z = make_float4(0.f, 0.f, 0.f, 0.f);
    for (int i = idx; i < n4; i += stride) out4[i] = z;
    for (int i = idx; i < N_NODES; i += stride) g_denom[i] = 0.f;
}

// ---------------------------------------------------------------------------
// K1: one warp per edge.
//   attn = exp(dot(emb[row], emb[col]))
//   denom[row] += attn            (scalar red)
//   agg[row]   += attn * emb[col] (vector red.v4)
// NOTE: edges is int32 (JAX default x64-disabled downcasts int64 -> int32).
// ---------------------------------------------------------------------------
__global__ void edge_kernel(const float4* __restrict__ emb4,
                            const int* __restrict__ edges,
                            float* __restrict__ agg) {
    int gwarp = (blockIdx.x * blockDim.x + threadIdx.x) >> 5;
    int lane = threadIdx.x & 31;
    if (gwarp >= N_EDGES) return;

    int r = edges[gwarp];            // destination (segment) node
    int c = edges[N_EDGES + gwarp];  // source node
    if ((unsigned)r >= N_NODES || (unsigned)c >= N_NODES) return;  // safety

    float4 a = emb4[(size_t)r * 32 + lane];
    float4 b = emb4[(size_t)c * 32 + lane];

    float p = a.x * b.x + a.y * b.y + a.z * b.z + a.w * b.w;
#pragma unroll
    for (int o = 16; o > 0; o >>= 1)
        p += __shfl_xor_sync(0xffffffffu, p, o);

    float w = expf(p);

    if (lane == 0) atomicAdd(&g_denom[r], w);

    float vx = w * b.x, vy = w * b.y, vz = w * b.z, vw = w * b.w;
    float* dst = agg + (size_t)r * DIM + lane * 4;
    asm volatile("red.global.add.v4.f32 [%0], {%1, %2, %3, %4};"
                 :: "l"(dst), "f"(vx), "f"(vy), "f"(vz), "f"(vw)
                 : "memory");
}

// ---------------------------------------------------------------------------
// K2: per-row  x = [emb[i], agg[i]/denom[i]] @ W^T + b ; out = LayerNorm(x)
// Persistent blocks. W transposed into smem once per block (Ws[k][j]).
// Tile = 32 rows, 256 threads, 4 cols x 4 rows register blocking per thread.
// smem: Ws 256*128 f32 (128KB) + xs 32*256 f32 (32KB) = 160KB dynamic.
// ---------------------------------------------------------------------------
#define TILE_R 32
#define GEMM_SMEM_BYTES ((256 * 128 + TILE_R * 256) * 4)

__global__ void __launch_bounds__(256, 1)
gemm_ln_kernel(const float* __restrict__ emb,
               const float* __restrict__ W,
               const float* __restrict__ bias,
               const float* __restrict__ gamma,
               const float* __restrict__ beta,
               float* __restrict__ out /* in: agg, out: final */) {
    extern __shared__ float smem[];
    float* Ws = smem;                 // [256][128]  Ws[k*128+j] = W[j*256+k]
    float* xs = smem + 256 * 128;     // [32][256] row-major x_cat tile

    const int tid = threadIdx.x;
    const int jq = tid & 31;   // output-column group: cols [jq*4, jq*4+4)
    const int rq = tid >> 5;   // row group (warp id): rows [rq*4, rq*4+4)

    // Stage W transposed (one time per block; 148 blocks total -> negligible)
    for (int idx = tid; idx < 128 * 256; idx += 256) {
        int j = idx >> 8;
        int k = idx & 255;
        Ws[k * 128 + j] = W[idx];
    }
    __syncthreads();

    const int ntiles = (N_NODES + TILE_R - 1) / TILE_R;
    for (int tile = blockIdx.x; tile < ntiles; tile += gridDim.x) {
        const int row0 = tile * TILE_R;

        // --- load x tile: warp rq loads rows rq*4 .. rq*4+3 ---
#pragma unroll
        for (int i = 0; i < 4; i++) {
            int r = rq * 4 + i;
            int row = row0 + r;
            float4 e4, a4;
            if (row < N_NODES) {
                e4 = reinterpret_cast<const float4*>(emb)[(size_t)row * 32 + jq];
                float inv_d = 1.0f / (g_denom[row] + 1e-20f);
                a4 = reinterpret_cast<const float4*>(out)[(size_t)row * 32 + jq];
                a4.x *= inv_d; a4.y *= inv_d; a4.z *= inv_d; a4.w *= inv_d;
            } else {
                e4 = make_float4(0.f, 0.f, 0.f, 0.f);
                a4 = e4;
            }
            reinterpret_cast<float4*>(xs + r * 256)[jq] = e4;
            reinterpret_cast<float4*>(xs + r * 256 + 128)[jq] = a4;
        }
        __syncthreads();

        // --- GEMM: acc[i][jj] = sum_k xs[rq*4+i][k] * Ws[k][jq*4+jj] ---
        float acc[4][4];
#pragma unroll
        for (int i = 0; i < 4; i++)
#pragma unroll
            for (int jj = 0; jj < 4; jj++) acc[i][jj] = 0.f;

#pragma unroll 4
        for (int k = 0; k < 256; k++) {
            const float4 w4 =
                *reinterpret_cast<const float4*>(&Ws[(k << 7) + (jq << 2)]);
#pragma unroll
            for (int i = 0; i < 4; i++) {
                float xv = xs[((rq << 2) + i) * 256 + k];
                acc[i][0] = fmaf(xv, w4.x, acc[i][0]);
                acc[i][1] = fmaf(xv, w4.y, acc[i][1]);
                acc[i][2] = fmaf(xv, w4.z, acc[i][2]);
                acc[i][3] = fmaf(xv, w4.w, acc[i][3]);
            }
        }
        __syncthreads();  // done reading xs; reuse as x-output buffer

        // --- add bias, stash x tile [32][128] into smem for LN ---
        const float4 b4 = reinterpret_cast<const float4*>(bias)[jq];
#pragma unroll
        for (int i = 0; i < 4; i++) {
            int r = rq * 4 + i;
            float4 v;
            v.x = acc[i][0] + b4.x;
            v.y = acc[i][1] + b4.y;
            v.z = acc[i][2] + b4.z;
            v.w = acc[i][3] + b4.w;
            reinterpret_cast<float4*>(xs + r * 128)[jq] = v;
        }
        __syncthreads();

        // --- LayerNorm: warp rq normalizes rows rq*4 .. rq*4+3 ---
        const float4 g4 = reinterpret_cast<const float4*>(gamma)[jq];
        const float4 be4 = reinterpret_cast<const float4*>(beta)[jq];
#pragma unroll
        for (int i = 0; i < 4; i++) {
            int r = rq * 4 + i;
            int row = row0 + r;
            float4 v = reinterpret_cast<float4*>(xs + r * 128)[jq];
            float s = v.x + v.y + v.z + v.w;
            float sq = v.x * v.x + v.y * v.y + v.z * v.z + v.w * v.w;
#pragma unroll
            for (int o = 16; o > 0; o >>= 1) {
                s += __shfl_xor_sync(0xffffffffu, s, o);
                sq += __shfl_xor_sync(0xffffffffu, sq, o);
            }
            float mu = s * (1.0f / 128.0f);
            float var = sq * (1.0f / 128.0f) - mu * mu;
            float rs = rsqrtf(var + 1e-5f);
            if (row < N_NODES) {
                float4 o4;
                o4.x = (v.x - mu) * rs * g4.x + be4.x;
                o4.y = (v.y - mu) * rs * g4.y + be4.y;
                o4.z = (v.z - mu) * rs * g4.z + be4.z;
                o4.w = (v.w - mu) * rs * g4.w + be4.w;
                reinterpret_cast<float4*>(out)[(size_t)row * 32 + jq] = o4;
            }
        }
        __syncthreads();  // before next tile overwrites xs
    }
}

// ---------------------------------------------------------------------------
extern "C" void kernel_launch(void* const* d_in, const int* in_sizes, int n_in,
                              void* d_out, int out_size) {
    const float* emb = (const float*)d_in[0];
    const int* edges = (const int*)d_in[1];   // int32! (JAX x64 disabled)
    const float* W = (const float*)d_in[2];
    const float* bias = (const float*)d_in[3];
    const float* gamma = (const float*)d_in[4];
    const float* beta = (const float*)d_in[5];
    float* out = (float*)d_out;

    (void)in_sizes; (void)n_in; (void)out_size;

    // K0: zero agg (in d_out) + denom
    zero_kernel<<<4096, 256>>>(reinterpret_cast<float4*>(out));

    // K1: edge attention + scatter-add (1 warp / edge)
    {
        int total_threads = N_EDGES * 32;
        int threads = 256;
        int blocks = (total_threads + threads - 1) / threads;
        edge_kernel<<<blocks, threads>>>(reinterpret_cast<const float4*>(emb),
                                         edges, out);
    }

    // K2: fused normalize + concat-GEMM + LayerNorm (persistent grid)
    cudaFuncSetAttribute(gemm_ln_kernel,
                         cudaFuncAttributeMaxDynamicSharedMemorySize,
                         GEMM_SMEM_BYTES);
    gemm_ln_kernel<<<148, 256, GEMM_SMEM_BYTES>>>(emb, W, bias, gamma, beta,
                                                  out);
}